// round 3
// baseline (speedup 1.0000x reference)
#include <cuda_runtime.h>
#include <math.h>

// Sizes (fixed by the problem)
#define BB 2
#define HH 8
#define NN 512      // sequence length
#define DD 64       // dim head
#define TT 512      // DFT input (nonzero) length
#define MM 512      // DFT output frequencies kept (m < n)
#define CC 2048     // GEMM columns: 2 tensors * (2*8) bh * 64 j

#define X_ELEMS   (BB*NN*512)   // 524288
#define W_ELEMS   (512*512)     // 262144
#define OUT_F2    (BB*HH*NN*DD) // 524288 complex outputs

__device__ __forceinline__ int iclamp(int i, int n) { return i < n ? (i < 0 ? 0 : i) : n - 1; }

// ---------------- scratch (__device__ globals; no allocation) ----------------
__device__ float g_kraw[BB*NN*512];   // x @ Wk   [1024, 512]
__device__ float g_v   [BB*NN*512];   // x @ Wv   [1024, 512]
__device__ float g_part[256];
__device__ float g_rnorm;
__device__ float g_Ac[MM*TT];         // cos(2pi m t / 1024)
__device__ float g_As[MM*TT];         // -sin(2pi m t / 1024)
__device__ float g_inb[TT*CC];        // DFT GEMM B: [t][c], c = sel*1024 + b*512 + h*64 + j
__device__ float g_re [MM*CC];        // Re P[m][c]
__device__ float g_im [MM*CC];        // Im P[m][c]

// ---------------- K0: build DFT matrices ----------------
__global__ void k_build_dft() {
    int m = blockIdx.x;
    int t = threadIdx.x;
    int k = (m * t) & 1023;           // exact phase reduction
    float s, c;
    sincospif((float)k * (1.0f / 512.0f), &s, &c);   // theta = 2*pi*k/1024
    g_Ac[m*TT + t] = c;
    g_As[m*TT + t] = -s;
}

// ---------------- K1: projections k = x@Wk, v = x@Wv ----------------
__global__ void k_proj(const float* __restrict__ X,
                       const float* __restrict__ Wkm,
                       const float* __restrict__ Wvm) {
    const int tidx = threadIdx.x;          // 256 threads
    const int tx = tidx & 15, ty = tidx >> 4;
    const int n0 = blockIdx.x * 64;
    const int m0 = blockIdx.y * 64;
    const float* Bm = blockIdx.z ? Wvm : Wkm;
    float* Cm = blockIdx.z ? g_v : g_kraw;

    __shared__ float sA[16][65];
    __shared__ float sB[16][64];
    float acc[4][4] = {};

    for (int k0 = 0; k0 < 512; k0 += 16) {
        int ak = tidx & 15, am = tidx >> 4;
#pragma unroll
        for (int i = 0; i < 4; i++)
            sA[ak][am + i*16] = X[iclamp((m0 + am + i*16)*512 + k0 + ak, X_ELEMS)];
        int bn = tidx & 63, bk = tidx >> 6;
#pragma unroll
        for (int i = 0; i < 4; i++)
            sB[bk + i*4][bn] = Bm[iclamp((k0 + bk + i*4)*512 + n0 + bn, W_ELEMS)];
        __syncthreads();
#pragma unroll
        for (int kk = 0; kk < 16; kk++) {
            float a4[4], b4[4];
#pragma unroll
            for (int r = 0; r < 4; r++) a4[r] = sA[kk][ty + 16*r];
#pragma unroll
            for (int c = 0; c < 4; c++) b4[c] = sB[kk][tx + 16*c];
#pragma unroll
            for (int r = 0; r < 4; r++)
#pragma unroll
                for (int c = 0; c < 4; c++)
                    acc[r][c] += a4[r] * b4[c];
        }
        __syncthreads();
    }
#pragma unroll
    for (int r = 0; r < 4; r++)
#pragma unroll
        for (int c = 0; c < 4; c++)
            Cm[(m0 + ty + 16*r)*512 + n0 + tx + 16*c] = acc[r][c];
}

// ---------------- K2: Frobenius norm of k (deterministic 2-stage) ----------------
__global__ void k_norm1() {
    __shared__ float sm[256];
    int base = blockIdx.x * 2048;
    float s = 0.f;
    for (int i = threadIdx.x; i < 2048; i += 256) {
        float x = g_kraw[base + i];
        s += x * x;
    }
    sm[threadIdx.x] = s; __syncthreads();
    for (int o = 128; o > 0; o >>= 1) {
        if (threadIdx.x < o) sm[threadIdx.x] += sm[threadIdx.x + o];
        __syncthreads();
    }
    if (threadIdx.x == 0) g_part[blockIdx.x] = sm[0];
}
__global__ void k_norm2() {
    __shared__ float sm[256];
    sm[threadIdx.x] = g_part[threadIdx.x]; __syncthreads();
    for (int o = 128; o > 0; o >>= 1) {
        if (threadIdx.x < o) sm[threadIdx.x] += sm[threadIdx.x + o];
        __syncthreads();
    }
    if (threadIdx.x == 0) g_rnorm = 1.0f / sqrtf(sm[0]);
}

// ---------------- K3: k_ = elu(k*rnorm); S_k per head; u = S_k*v; pack B ----------------
__global__ void k_prep() {
    int bt = blockIdx.x;           // b*512 + t
    int b  = bt >> 9;
    int t  = bt & 511;
    int c  = threadIdx.x;          // 0..511 = h*64 + j
    float rn = g_rnorm;
    float kv = g_kraw[bt*512 + c] * rn;
    float ke = kv > 0.f ? kv : expm1f(kv);

    float s = ke;
#pragma unroll
    for (int o = 16; o > 0; o >>= 1) s += __shfl_down_sync(0xffffffffu, s, o);
    __shared__ float wsum[16];
    __shared__ float hsum[8];
    int warp = c >> 5;
    if ((c & 31) == 0) wsum[warp] = s;
    __syncthreads();
    if (c < 8) hsum[c] = wsum[2*c] + wsum[2*c + 1];
    __syncthreads();

    int h = c >> 6;
    float u = hsum[h] * g_v[bt*512 + c];
    g_inb[t*CC + b*512 + c]        = u;    // numerator tensor (sel 0)
    g_inb[t*CC + 1024 + b*512 + c] = ke;   // denominator tensor (sel 1)
}

// ---------------- K4: dual DFT GEMM: [512 x 512] (cos,sin) @ [512 x 2048] ----------------
__global__ void k_dft() {
    const int tidx = threadIdx.x;          // 256 threads
    const int tx = tidx & 15, ty = tidx >> 4;
    const int n0 = blockIdx.x * 64;        // col
    const int m0 = blockIdx.y * 64;        // freq

    __shared__ float sAc[16][65];
    __shared__ float sAs[16][65];
    __shared__ float sB[16][64];
    float ar[4][4] = {};
    float ai[4][4] = {};

    for (int k0 = 0; k0 < 512; k0 += 16) {
        int ak = tidx & 15, am = tidx >> 4;
#pragma unroll
        for (int i = 0; i < 4; i++) {
            int idx = (m0 + am + i*16)*TT + k0 + ak;
            sAc[ak][am + i*16] = g_Ac[idx];
            sAs[ak][am + i*16] = g_As[idx];
        }
        int bn = tidx & 63, bk = tidx >> 6;
#pragma unroll
        for (int i = 0; i < 4; i++)
            sB[bk + i*4][bn] = g_inb[(k0 + bk + i*4)*CC + n0 + bn];
        __syncthreads();
#pragma unroll
        for (int kk = 0; kk < 16; kk++) {
            float c4[4], s4[4], b4[4];
#pragma unroll
            for (int r = 0; r < 4; r++) {
                c4[r] = sAc[kk][ty + 16*r];
                s4[r] = sAs[kk][ty + 16*r];
            }
#pragma unroll
            for (int c = 0; c < 4; c++) b4[c] = sB[kk][tx + 16*c];
#pragma unroll
            for (int r = 0; r < 4; r++)
#pragma unroll
                for (int c = 0; c < 4; c++) {
                    ar[r][c] += c4[r] * b4[c];
                    ai[r][c] += s4[r] * b4[c];
                }
        }
        __syncthreads();
    }
#pragma unroll
    for (int r = 0; r < 4; r++)
#pragma unroll
        for (int c = 0; c < 4; c++) {
            int o = (m0 + ty + 16*r)*CC + n0 + tx + 16*c;
            g_re[o] = ar[r][c];
            g_im[o] = ai[r][c];
        }
}

// ---------------- K5: (b,h) 2x8 DFT mix + complex division + store ----------------
// mode 0: real part only (out_size < 2*OUT_F2 floats)
// mode 1: interleaved (re, im) float pairs
__global__ void k_mix(float* __restrict__ out, int cap_floats, int mode) {
    int m = blockIdx.x;      // 0..511
    int j = threadIdx.x;     // 0..63

    float pur[16], pui[16], pkr[16], pki[16];
#pragma unroll
    for (int bh = 0; bh < 16; bh++) {
        int cu = m*CC + bh*64 + j;
        pur[bh] = g_re[cu];        pui[bh] = g_im[cu];
        pkr[bh] = g_re[cu + 1024]; pki[bh] = g_im[cu + 1024];
    }

    const float R2 = 0.70710678118654752f;
    const float w8r[8] = {1.f,  R2, 0.f, -R2, -1.f, -R2, 0.f,  R2};
    const float w8i[8] = {0.f, -R2, -1.f, -R2, 0.f,  R2, 1.f,  R2};

#pragma unroll
    for (int h0 = 0; h0 < 8; h0++) {
        float eur=0,eui=0,our_=0,oui=0, ekr=0,eki=0,okr=0,oki=0;
#pragma unroll
        for (int hp = 0; hp < 8; hp++) {
            int kq = (h0 * hp) & 7;
            float wr = w8r[kq], wi = w8i[kq];
            eur  += wr*pur[hp]   - wi*pui[hp];
            eui  += wr*pui[hp]   + wi*pur[hp];
            our_ += wr*pur[8+hp] - wi*pui[8+hp];
            oui  += wr*pui[8+hp] + wi*pur[8+hp];
            ekr  += wr*pkr[hp]   - wi*pki[hp];
            eki  += wr*pki[hp]   + wi*pkr[hp];
            okr  += wr*pkr[8+hp] - wi*pki[8+hp];
            oki  += wr*pki[8+hp] + wi*pkr[8+hp];
        }
#pragma unroll
        for (int b0 = 0; b0 < 2; b0++) {
            float sg = b0 ? -1.f : 1.f;
            float nr = eur + sg*our_, ni = eui + sg*oui;
            float dr = ekr + sg*okr,  di = eki + sg*oki;
            float inv = 1.0f / (dr*dr + di*di);
            float orr = (nr*dr + ni*di) * inv;
            float oii = (ni*dr - nr*di) * inv;
            int idx = (((b0*8 + h0)*512 + m)*64) + j;   // complex index
            if (mode) {
                int f = 2*idx;
                if (f + 1 < cap_floats) { out[f] = orr; out[f+1] = oii; }
            } else {
                if (idx < cap_floats) out[idx] = orr;
            }
        }
    }
}

// ---------------- launch ----------------
extern "C" void kernel_launch(void* const* d_in, const int* in_sizes, int n_in,
                              void* d_out, int out_size) {
    // Input identification (element-count semantics per harness docs):
    //   x = largest input; Wq,Wk,Wv = the three inputs sharing a size occurring 3x.
    const float* x = nullptr;
    const float* Ws[3] = {nullptr, nullptr, nullptr};

    int xi = -1; long long xmax = -1;
    for (int i = 0; i < n_in; i++)
        if ((long long)in_sizes[i] > xmax) { xmax = in_sizes[i]; xi = i; }
    if (xi >= 0) x = (const float*)d_in[xi];

    int wcount = 0;
    for (int i = 0; i < n_in && wcount < 3; i++) {
        if (i == xi) continue;
        int same = 0;
        for (int k2 = 0; k2 < n_in; k2++)
            if (k2 != xi && in_sizes[k2] == in_sizes[i]) same++;
        if (same == 3) Ws[wcount++] = (const float*)d_in[i];
    }
    if ((!Ws[0] || !Ws[1] || !Ws[2]) && n_in >= 4) {   // positional fallback
        x = (const float*)d_in[0];
        Ws[0] = (const float*)d_in[1];
        Ws[1] = (const float*)d_in[2];
        Ws[2] = (const float*)d_in[3];
    }
    const float* Wk = Ws[1];
    const float* Wv = Ws[2];
    if (!x || !Wk || !Wv || !d_out || out_size <= 0) return;

    // Output semantics adapt to out_size (host value):
    //   out_size >= 2*OUT_F2  -> interleaved (re,im) float pairs
    //   otherwise             -> real part only
    // Every store is bounded by cap_floats <= out_size, so no interpretation faults.
    int mode, cap_floats;
    if (out_size >= 2*OUT_F2) { mode = 1; cap_floats = 2*OUT_F2; }
    else                      { mode = 0; cap_floats = out_size < OUT_F2 ? out_size : OUT_F2; }

    k_build_dft<<<512, 512>>>();
    k_proj<<<dim3(8, 16, 2), 256>>>(x, Wk, Wv);
    k_norm1<<<256, 256>>>();
    k_norm2<<<1, 256>>>();
    k_prep<<<1024, 512>>>();
    k_dft<<<dim3(32, 8), 256>>>();
    k_mix<<<512, 64>>>((float*)d_out, cap_floats, mode);
}

// round 4
// speedup vs baseline: 1.1854x; 1.1854x over previous
#include <cuda_runtime.h>
#include <math.h>

#define BB 2
#define HH 8
#define NN 512
#define DD 64
#define TT 512      // DFT input (nonzero) length
#define MM 512      // DFT output frequencies kept
#define CC 2048     // GEMM columns: 2 tensors * 16 bh * 64 j

#define X_ELEMS   (BB*NN*512)   // 524288
#define W_ELEMS   (512*512)     // 262144
#define OUT_F2    (BB*HH*NN*DD) // 524288 complex outputs

__device__ __forceinline__ int iclamp(int i, int n) { return i < n ? (i < 0 ? 0 : i) : n - 1; }

// ---------------- scratch ----------------
__device__ float g_kraw[BB*NN*512];
__device__ float g_v   [BB*NN*512];
__device__ float g_part[256];
__device__ float g_rnorm;
__device__ float g_Ac[256*TT];        // cos rows m=0..255 only (pairing covers the rest)
__device__ float g_As[256*TT];        // -sin rows m=0..255
__device__ float g_inb[TT*CC];
__device__ float g_re [MM*CC];
__device__ float g_im [MM*CC];

// ---------------- K0: build DFT matrix rows 0..255 ----------------
__global__ void k_build_dft() {
    int m = blockIdx.x;               // 0..255
    int t = threadIdx.x;              // 0..511
    int k = (m * t) & 1023;
    float s, c;
    sincospif((float)k * (1.0f / 512.0f), &s, &c);
    g_Ac[m*TT + t] = c;
    g_As[m*TT + t] = -s;
}

// ---------------- K1: merged projections k = x@Wk, v = x@Wv ----------------
__global__ void k_proj(const float* __restrict__ X,
                       const float* __restrict__ Wkm,
                       const float* __restrict__ Wvm) {
    const int tidx = threadIdx.x;          // 256 threads
    const int tx = tidx & 15, ty = tidx >> 4;
    const int n0 = blockIdx.x * 64;
    const int m0 = blockIdx.y * 64;

    __shared__ float sA [16][65];
    __shared__ float sBk[16][64];
    __shared__ float sBv[16][64];
    float ack[4][4] = {};
    float acv[4][4] = {};

    for (int k0 = 0; k0 < 512; k0 += 16) {
        int ak = tidx & 15, am = tidx >> 4;
#pragma unroll
        for (int i = 0; i < 4; i++)
            sA[ak][am + i*16] = X[iclamp((m0 + am + i*16)*512 + k0 + ak, X_ELEMS)];
        int bn = tidx & 63, bk = tidx >> 6;
#pragma unroll
        for (int i = 0; i < 4; i++) {
            int widx = iclamp((k0 + bk + i*4)*512 + n0 + bn, W_ELEMS);
            sBk[bk + i*4][bn] = Wkm[widx];
            sBv[bk + i*4][bn] = Wvm[widx];
        }
        __syncthreads();
#pragma unroll
        for (int kk = 0; kk < 16; kk++) {
            float a4[4], bk4[4], bv4[4];
#pragma unroll
            for (int r = 0; r < 4; r++) a4[r] = sA[kk][ty + 16*r];
#pragma unroll
            for (int c = 0; c < 4; c++) { bk4[c] = sBk[kk][tx + 16*c]; bv4[c] = sBv[kk][tx + 16*c]; }
#pragma unroll
            for (int r = 0; r < 4; r++)
#pragma unroll
                for (int c = 0; c < 4; c++) {
                    ack[r][c] += a4[r] * bk4[c];
                    acv[r][c] += a4[r] * bv4[c];
                }
        }
        __syncthreads();
    }
#pragma unroll
    for (int r = 0; r < 4; r++)
#pragma unroll
        for (int c = 0; c < 4; c++) {
            int o = (m0 + ty + 16*r)*512 + n0 + tx + 16*c;
            g_kraw[o] = ack[r][c];
            g_v[o]    = acv[r][c];
        }
}

// ---------------- K2: Frobenius norm (deterministic 2-stage) ----------------
__global__ void k_norm1() {
    __shared__ float sm[256];
    int base = blockIdx.x * 2048;
    float s = 0.f;
    for (int i = threadIdx.x; i < 2048; i += 256) {
        float x = g_kraw[base + i];
        s += x * x;
    }
    sm[threadIdx.x] = s; __syncthreads();
    for (int o = 128; o > 0; o >>= 1) {
        if (threadIdx.x < o) sm[threadIdx.x] += sm[threadIdx.x + o];
        __syncthreads();
    }
    if (threadIdx.x == 0) g_part[blockIdx.x] = sm[0];
}
__global__ void k_norm2() {
    __shared__ float sm[256];
    sm[threadIdx.x] = g_part[threadIdx.x]; __syncthreads();
    for (int o = 128; o > 0; o >>= 1) {
        if (threadIdx.x < o) sm[threadIdx.x] += sm[threadIdx.x + o];
        __syncthreads();
    }
    if (threadIdx.x == 0) g_rnorm = 1.0f / sqrtf(sm[0]);
}

// ---------------- K3: elu, per-head sums, pack B ----------------
__global__ void k_prep() {
    int bt = blockIdx.x;           // b*512 + t
    int b  = bt >> 9;
    int t  = bt & 511;
    int c  = threadIdx.x;          // 0..511 = h*64 + j
    float rn = g_rnorm;
    float kv = g_kraw[bt*512 + c] * rn;
    float ke = kv > 0.f ? kv : expm1f(kv);

    float s = ke;
#pragma unroll
    for (int o = 16; o > 0; o >>= 1) s += __shfl_down_sync(0xffffffffu, s, o);
    __shared__ float wsum[16];
    __shared__ float hsum[8];
    int warp = c >> 5;
    if ((c & 31) == 0) wsum[warp] = s;
    __syncthreads();
    if (c < 8) hsum[c] = wsum[2*c] + wsum[2*c + 1];
    __syncthreads();

    int h = c >> 6;
    float u = hsum[h] * g_v[bt*512 + c];
    g_inb[t*CC + b*512 + c]        = u;    // numerator tensor
    g_inb[t*CC + 1024 + b*512 + c] = ke;   // denominator tensor
}

// ---------------- K4: paired dual-DFT GEMM (rows m and 512-m together) ----------------
// Parity split over t: Ac[512-m][t] = (-1)^t Ac[m][t], As[512-m][t] = -(-1)^t As[m][t]
__global__ void k_dft() {
    const int tidx = threadIdx.x;          // 256 threads
    const int tx = tidx & 15, ty = tidx >> 4;
    const int n0 = blockIdx.x * 64;        // col
    const int m0 = blockIdx.y * 64;        // primary freq row base (by < 4 -> m in 0..255)

    __shared__ float sAc[16][65];
    __shared__ float sAs[16][65];
    __shared__ float sB [16][64];
    float are[4][4] = {}, aro[4][4] = {};  // Re accum, even/odd t
    float aie[4][4] = {}, aio[4][4] = {};  // Im accum, even/odd t

    for (int k0 = 0; k0 < 512; k0 += 16) {
        int ak = tidx & 15, am = tidx >> 4;
#pragma unroll
        for (int i = 0; i < 4; i++) {
            int idx = (m0 + am + i*16)*TT + k0 + ak;
            sAc[ak][am + i*16] = g_Ac[idx];
            sAs[ak][am + i*16] = g_As[idx];
        }
        int bn = tidx & 63, bk = tidx >> 6;
#pragma unroll
        for (int i = 0; i < 4; i++)
            sB[bk + i*4][bn] = g_inb[(k0 + bk + i*4)*CC + n0 + bn];
        __syncthreads();
#pragma unroll
        for (int kk = 0; kk < 16; kk++) {     // t = k0+kk; parity = kk&1 (k0 even)
            float c4[4], s4[4], b4[4];
#pragma unroll
            for (int r = 0; r < 4; r++) {
                c4[r] = sAc[kk][ty + 16*r];
                s4[r] = sAs[kk][ty + 16*r];
            }
#pragma unroll
            for (int c = 0; c < 4; c++) b4[c] = sB[kk][tx + 16*c];
            if ((kk & 1) == 0) {
#pragma unroll
                for (int r = 0; r < 4; r++)
#pragma unroll
                    for (int c = 0; c < 4; c++) {
                        are[r][c] += c4[r] * b4[c];
                        aie[r][c] += s4[r] * b4[c];
                    }
            } else {
#pragma unroll
                for (int r = 0; r < 4; r++)
#pragma unroll
                    for (int c = 0; c < 4; c++) {
                        aro[r][c] += c4[r] * b4[c];
                        aio[r][c] += s4[r] * b4[c];
                    }
            }
        }
        __syncthreads();
    }
#pragma unroll
    for (int r = 0; r < 4; r++)
#pragma unroll
        for (int c = 0; c < 4; c++) {
            int mp  = m0 + ty + 16*r;                 // 0..255
            int col = n0 + tx + 16*c;
            int o1 = mp*CC + col;
            g_re[o1] = are[r][c] + aro[r][c];
            g_im[o1] = aie[r][c] + aio[r][c];
            int mq = 512 - mp;                        // 257..512
            if (mq < MM) {
                int o2 = mq*CC + col;
                g_re[o2] = are[r][c] - aro[r][c];
                g_im[o2] = aio[r][c] - aie[r][c];
            }
        }
}

// ---------------- K4b: row m=256 (cos/sin are 0/±1 patterns) ----------------
__global__ void k_dft256() {
    int c = blockIdx.x * 256 + threadIdx.x;   // 0..2047
    float re = 0.f, im = 0.f;
#pragma unroll 4
    for (int t = 0; t < 512; t += 4) {
        re += g_inb[t*CC + c]       - g_inb[(t+2)*CC + c];
        im += g_inb[(t+3)*CC + c]   - g_inb[(t+1)*CC + c];
    }
    g_re[256*CC + c] = re;
    g_im[256*CC + c] = im;
}

// ---------------- K5: (b,h) 2x8 DFT mix + complex division ----------------
__global__ void k_mix(float* __restrict__ out, int cap_floats, int mode) {
    int m = blockIdx.x;      // 0..511
    int j = threadIdx.x;     // 0..63

    float pur[16], pui[16], pkr[16], pki[16];
#pragma unroll
    for (int bh = 0; bh < 16; bh++) {
        int cu = m*CC + bh*64 + j;
        pur[bh] = g_re[cu];        pui[bh] = g_im[cu];
        pkr[bh] = g_re[cu + 1024]; pki[bh] = g_im[cu + 1024];
    }

    const float R2 = 0.70710678118654752f;
    const float w8r[8] = {1.f,  R2, 0.f, -R2, -1.f, -R2, 0.f,  R2};
    const float w8i[8] = {0.f, -R2, -1.f, -R2, 0.f,  R2, 1.f,  R2};

#pragma unroll
    for (int h0 = 0; h0 < 8; h0++) {
        float eur=0,eui=0,our_=0,oui=0, ekr=0,eki=0,okr=0,oki=0;
#pragma unroll
        for (int hp = 0; hp < 8; hp++) {
            int kq = (h0 * hp) & 7;
            float wr = w8r[kq], wi = w8i[kq];
            eur  += wr*pur[hp]   - wi*pui[hp];
            eui  += wr*pui[hp]   + wi*pur[hp];
            our_ += wr*pur[8+hp] - wi*pui[8+hp];
            oui  += wr*pui[8+hp] + wi*pur[8+hp];
            ekr  += wr*pkr[hp]   - wi*pki[hp];
            eki  += wr*pki[hp]   + wi*pkr[hp];
            okr  += wr*pkr[8+hp] - wi*pki[8+hp];
            oki  += wr*pki[8+hp] + wi*pkr[8+hp];
        }
#pragma unroll
        for (int b0 = 0; b0 < 2; b0++) {
            float sg = b0 ? -1.f : 1.f;
            float nr = eur + sg*our_, ni = eui + sg*oui;
            float dr = ekr + sg*okr,  di = eki + sg*oki;
            float inv = 1.0f / (dr*dr + di*di);
            float orr = (nr*dr + ni*di) * inv;
            float oii = (ni*dr - nr*di) * inv;
            int idx = (((b0*8 + h0)*512 + m)*64) + j;
            if (mode) {
                int f = 2*idx;
                if (f + 1 < cap_floats) { out[f] = orr; out[f+1] = oii; }
            } else {
                if (idx < cap_floats) out[idx] = orr;
            }
        }
    }
}

// ---------------- launch ----------------
extern "C" void kernel_launch(void* const* d_in, const int* in_sizes, int n_in,
                              void* d_out, int out_size) {
    const float* x = nullptr;
    const float* Ws[3] = {nullptr, nullptr, nullptr};

    int xi = -1; long long xmax = -1;
    for (int i = 0; i < n_in; i++)
        if ((long long)in_sizes[i] > xmax) { xmax = in_sizes[i]; xi = i; }
    if (xi >= 0) x = (const float*)d_in[xi];

    int wcount = 0;
    for (int i = 0; i < n_in && wcount < 3; i++) {
        if (i == xi) continue;
        int same = 0;
        for (int k2 = 0; k2 < n_in; k2++)
            if (k2 != xi && in_sizes[k2] == in_sizes[i]) same++;
        if (same == 3) Ws[wcount++] = (const float*)d_in[i];
    }
    if ((!Ws[0] || !Ws[1] || !Ws[2]) && n_in >= 4) {
        x = (const float*)d_in[0];
        Ws[0] = (const float*)d_in[1];
        Ws[1] = (const float*)d_in[2];
        Ws[2] = (const float*)d_in[3];
    }
    const float* Wk = Ws[1];
    const float* Wv = Ws[2];
    if (!x || !Wk || !Wv || !d_out || out_size <= 0) return;

    int mode, cap_floats;
    if (out_size >= 2*OUT_F2) { mode = 1; cap_floats = 2*OUT_F2; }
    else                      { mode = 0; cap_floats = out_size < OUT_F2 ? out_size : OUT_F2; }

    k_build_dft<<<256, 512>>>();
    k_proj<<<dim3(8, 16), 256>>>(x, Wk, Wv);
    k_norm1<<<256, 256>>>();
    k_norm2<<<1, 256>>>();
    k_prep<<<1024, 512>>>();
    k_dft<<<dim3(32, 4), 256>>>();
    k_dft256<<<8, 256>>>();
    k_mix<<<512, 64>>>((float*)d_out, cap_floats, mode);
}